// round 1
// baseline (speedup 1.0000x reference)
#include <cuda_runtime.h>

// Problem constants (match reference)
#define NN       150000        // total nodes (users + items)
#define DIM      64
#define NE       4800000       // edges
#define NB       147           // ceil(NN / 1024)

// ---------------- scratch (device globals; no allocation allowed) ------------
__device__ int   g_cnt[NN];
__device__ int   g_rowptr[NN + 1];
__device__ int   g_cursor[NN];
__device__ int   g_bsum[NB];
__device__ int2  g_edge[NE];             // packed {col, float_as_int(val)}
__device__ float g_xa[(size_t)NN * DIM];
__device__ float g_xb[(size_t)NN * DIM];

// ---------------- CSR build ---------------------------------------------------
__global__ void k_zero_cnt() {
    int i = blockIdx.x * blockDim.x + threadIdx.x;
    for (; i < NN; i += gridDim.x * blockDim.x) g_cnt[i] = 0;
}

__global__ void k_hist(const int* __restrict__ rows) {
    int i = blockIdx.x * blockDim.x + threadIdx.x;
    for (; i < NE; i += gridDim.x * blockDim.x)
        atomicAdd(&g_cnt[rows[i]], 1);
}

// per-1024-chunk sums (147 blocks x 256 threads)
__global__ void k_chunksum() {
    __shared__ int sh[256];
    int b = blockIdx.x, t = threadIdx.x;
    int base = b * 1024;
    int s = 0;
    #pragma unroll
    for (int k = 0; k < 4; k++) {
        int i = base + t + k * 256;
        if (i < NN) s += g_cnt[i];
    }
    sh[t] = s;
    __syncthreads();
    for (int off = 128; off > 0; off >>= 1) {
        if (t < off) sh[t] += sh[t + off];
        __syncthreads();
    }
    if (t == 0) g_bsum[b] = sh[0];
}

// exclusive scan of the 147 chunk sums (1 block)
__global__ void k_scan_bsum() {
    __shared__ int sh[256];
    int t = threadIdx.x;
    int v = (t < NB) ? g_bsum[t] : 0;
    sh[t] = v;
    __syncthreads();
    for (int off = 1; off < 256; off <<= 1) {
        int add = (t >= off) ? sh[t - off] : 0;
        __syncthreads();
        sh[t] += add;
        __syncthreads();
    }
    if (t < NB) g_bsum[t] = sh[t] - v;   // exclusive
}

// per-chunk exclusive scan + add chunk offset -> rowptr, cursor
__global__ void k_writeptr() {
    __shared__ int sh[1024];
    int b = blockIdx.x, t = threadIdx.x;
    int i = b * 1024 + t;
    int v = (i < NN) ? g_cnt[i] : 0;
    sh[t] = v;
    __syncthreads();
    for (int off = 1; off < 1024; off <<= 1) {
        int add = (t >= off) ? sh[t - off] : 0;
        __syncthreads();
        sh[t] += add;
        __syncthreads();
    }
    int incl = sh[t];
    if (i < NN) {
        int rp = g_bsum[b] + (incl - v);
        g_rowptr[i] = rp;
        g_cursor[i] = rp;
        if (i == NN - 1) g_rowptr[NN] = g_bsum[b] + incl;   // == NE
    }
}

__global__ void k_scatter(const int* __restrict__ rows,
                          const int* __restrict__ cols,
                          const float* __restrict__ vals) {
    int i = blockIdx.x * blockDim.x + threadIdx.x;
    for (; i < NE; i += gridDim.x * blockDim.x) {
        int r = rows[i];
        int pos = atomicAdd(&g_cursor[r], 1);
        g_edge[pos] = make_int2(cols[i], __float_as_int(vals[i]));
    }
}

// ---------------- SpMM layer: warp-per-row, no atomics ------------------------
// y[row] = sum_e val_e * x[col_e];   xout = y;   out (+)= coeff * y  (+ emb on first)
__global__ void __launch_bounds__(256)
k_spmm(const float* __restrict__ xin, float* __restrict__ xout,
       float* __restrict__ out, const float* __restrict__ emb,
       float coeff, int first) {
    int gw = (blockIdx.x * blockDim.x + threadIdx.x) >> 5;
    if (gw >= NN) return;
    int lane = threadIdx.x & 31;

    int s = g_rowptr[gw];
    int e = g_rowptr[gw + 1];

    float2 acc = make_float2(0.f, 0.f);
    int base = s;

    // full 32-edge chunks: coalesced edge load, shfl-broadcast, unrolled gathers
    for (; base + 32 <= e; base += 32) {
        int2 ed = g_edge[base + lane];
        #pragma unroll
        for (int j = 0; j < 32; j++) {
            int   cj = __shfl_sync(0xffffffffu, ed.x, j);
            float vj = __int_as_float(__shfl_sync(0xffffffffu, ed.y, j));
            float2 xv = *reinterpret_cast<const float2*>(
                &xin[(size_t)cj * DIM + lane * 2]);
            acc.x = fmaf(vj, xv.x, acc.x);
            acc.y = fmaf(vj, xv.y, acc.y);
        }
    }
    // remainder
    if (base < e) {
        int rem = e - base;
        int2 ed = (base + lane < e) ? g_edge[base + lane] : make_int2(0, 0);
        for (int j = 0; j < rem; j++) {
            int   cj = __shfl_sync(0xffffffffu, ed.x, j);
            float vj = __int_as_float(__shfl_sync(0xffffffffu, ed.y, j));
            float2 xv = *reinterpret_cast<const float2*>(
                &xin[(size_t)cj * DIM + lane * 2]);
            acc.x = fmaf(vj, xv.x, acc.x);
            acc.y = fmaf(vj, xv.y, acc.y);
        }
    }

    size_t o = (size_t)gw * DIM + lane * 2;
    *reinterpret_cast<float2*>(&xout[o]) = acc;

    float2 basev;
    if (first) {
        basev = *reinterpret_cast<const float2*>(&emb[o]);
    } else {
        basev = *reinterpret_cast<const float2*>(&out[o]);
    }
    float2 ov;
    ov.x = fmaf(coeff, acc.x, basev.x);
    ov.y = fmaf(coeff, acc.y, basev.y);
    *reinterpret_cast<float2*>(&out[o]) = ov;
}

// ---------------- launch ------------------------------------------------------
extern "C" void kernel_launch(void* const* d_in, const int* in_sizes, int n_in,
                              void* d_out, int out_size) {
    const int*   rows = (const int*)d_in[0];
    const int*   cols = (const int*)d_in[1];
    const float* vals = (const float*)d_in[2];
    const float* emb  = (const float*)d_in[3];
    float*       out  = (float*)d_out;

    (void)in_sizes; (void)n_in; (void)out_size;

    // Resolve device-symbol addresses for the ping-pong buffers
    // (g_xa / g_xb are referenced directly inside kernels; for kernel args we
    //  pass pointers obtained via a tiny helper kernel-free trick: take the
    //  address in device code via the globals themselves.)
    // We get them with cudaGetSymbolAddress (query only; no allocation).
    static float* xa = nullptr;
    static float* xb = nullptr;
    if (!xa) {
        void* p;
        cudaGetSymbolAddress(&p, g_xa); xa = (float*)p;
        cudaGetSymbolAddress(&p, g_xb); xb = (float*)p;
    }

    // ---- CSR build (every launch; deterministic work) ----
    k_zero_cnt<<<256, 256>>>();
    k_hist<<<2048, 256>>>(rows);
    k_chunksum<<<NB, 256>>>();
    k_scan_bsum<<<1, 256>>>();
    k_writeptr<<<NB, 1024>>>();
    k_scatter<<<2048, 256>>>(rows, cols, vals);

    // ---- 3 SpMM layers, fused output accumulation ----
    const int threads = 256;
    const int blocks  = (NN * 32 + threads - 1) / threads;  // warp per row

    // layer 1: y1 = A @ emb ; out = emb + y1/2 ; xa = y1
    k_spmm<<<blocks, threads>>>(emb, xa, out, emb, 1.0f / 2.0f, 1);
    // layer 2: y2 = A @ y1 ; out += y2/3 ; xb = y2
    k_spmm<<<blocks, threads>>>(xa, xb, out, emb, 1.0f / 3.0f, 0);
    // layer 3: y3 = A @ y2 ; out += y3/4 ; xa = y3 (scratch)
    k_spmm<<<blocks, threads>>>(xb, xa, out, emb, 1.0f / 4.0f, 0);
}

// round 2
// speedup vs baseline: 1.0112x; 1.0112x over previous
#include <cuda_runtime.h>
#include <cuda_fp16.h>

// Problem constants (match reference)
#define NN       150000        // total nodes (users + items)
#define DIM      64
#define NE       4800000       // edges
#define NB       147           // ceil(NN / 1024)

// ---------------- scratch (device globals; no allocation allowed) ------------
__device__ int    g_cnt[NN];
__device__ int    g_rowptr[NN + 1];
__device__ int    g_cursor[NN];
__device__ int    g_bsum[NB];
__device__ int2   g_edge[NE];                 // packed {col, float_as_int(val)}
__device__ __half g_h0[(size_t)NN * DIM];     // emb_h (layer1 in), then y2 (layer3 in)
__device__ __half g_h1[(size_t)NN * DIM];     // y1 (layer2 in)

// ---------------- CSR build ---------------------------------------------------
__global__ void k_zero_cnt() {
    int i = blockIdx.x * blockDim.x + threadIdx.x;
    for (; i < NN; i += gridDim.x * blockDim.x) g_cnt[i] = 0;
}

__global__ void k_hist(const int* __restrict__ rows) {
    int i = blockIdx.x * blockDim.x + threadIdx.x;
    for (; i < NE; i += gridDim.x * blockDim.x)
        atomicAdd(&g_cnt[rows[i]], 1);
}

__global__ void k_chunksum() {
    __shared__ int sh[256];
    int b = blockIdx.x, t = threadIdx.x;
    int base = b * 1024;
    int s = 0;
    #pragma unroll
    for (int k = 0; k < 4; k++) {
        int i = base + t + k * 256;
        if (i < NN) s += g_cnt[i];
    }
    sh[t] = s;
    __syncthreads();
    for (int off = 128; off > 0; off >>= 1) {
        if (t < off) sh[t] += sh[t + off];
        __syncthreads();
    }
    if (t == 0) g_bsum[b] = sh[0];
}

__global__ void k_scan_bsum() {
    __shared__ int sh[256];
    int t = threadIdx.x;
    int v = (t < NB) ? g_bsum[t] : 0;
    sh[t] = v;
    __syncthreads();
    for (int off = 1; off < 256; off <<= 1) {
        int add = (t >= off) ? sh[t - off] : 0;
        __syncthreads();
        sh[t] += add;
        __syncthreads();
    }
    if (t < NB) g_bsum[t] = sh[t] - v;   // exclusive
}

__global__ void k_writeptr() {
    __shared__ int sh[1024];
    int b = blockIdx.x, t = threadIdx.x;
    int i = b * 1024 + t;
    int v = (i < NN) ? g_cnt[i] : 0;
    sh[t] = v;
    __syncthreads();
    for (int off = 1; off < 1024; off <<= 1) {
        int add = (t >= off) ? sh[t - off] : 0;
        __syncthreads();
        sh[t] += add;
        __syncthreads();
    }
    int incl = sh[t];
    if (i < NN) {
        int rp = g_bsum[b] + (incl - v);
        g_rowptr[i] = rp;
        g_cursor[i] = rp;
        if (i == NN - 1) g_rowptr[NN] = g_bsum[b] + incl;   // == NE
    }
}

__global__ void k_scatter(const int* __restrict__ rows,
                          const int* __restrict__ cols,
                          const float* __restrict__ vals) {
    int i = blockIdx.x * blockDim.x + threadIdx.x;
    for (; i < NE; i += gridDim.x * blockDim.x) {
        int r = rows[i];
        int pos = atomicAdd(&g_cursor[r], 1);
        g_edge[pos] = make_int2(cols[i], __float_as_int(vals[i]));
    }
}

// ---------------- emb fp32 -> fp16 conversion --------------------------------
__global__ void k_conv_emb(const float* __restrict__ emb) {
    // 9.6M elements; process 4 per thread
    int i = blockIdx.x * blockDim.x + threadIdx.x;
    const int total4 = (NN * DIM) / 4;
    for (; i < total4; i += gridDim.x * blockDim.x) {
        float4 f = *reinterpret_cast<const float4*>(&emb[(size_t)i * 4]);
        __half2 h0 = __floats2half2_rn(f.x, f.y);
        __half2 h1 = __floats2half2_rn(f.z, f.w);
        *reinterpret_cast<__half2*>(&g_h0[(size_t)i * 4])     = h0;
        *reinterpret_cast<__half2*>(&g_h0[(size_t)i * 4 + 2]) = h1;
    }
}

// ---------------- SpMM layer: warp-per-row, fp16 gather, fp32 accum -----------
// y[row] = sum_e val_e * x[col_e]
// if write_x: xout[row] = (half)y
// out[row] = base + coeff*y  where base = emb[row] (first) or out[row]
__global__ void __launch_bounds__(256)
k_spmm(const __half* __restrict__ xin, __half* __restrict__ xout,
       float* __restrict__ out, const float* __restrict__ emb,
       float coeff, int first, int write_x) {
    int gw = (blockIdx.x * blockDim.x + threadIdx.x) >> 5;
    if (gw >= NN) return;
    int lane = threadIdx.x & 31;

    int s = g_rowptr[gw];
    int e = g_rowptr[gw + 1];

    float2 acc = make_float2(0.f, 0.f);
    int base = s;

    for (; base + 32 <= e; base += 32) {
        int2 ed = g_edge[base + lane];
        #pragma unroll
        for (int j = 0; j < 32; j++) {
            int   cj = __shfl_sync(0xffffffffu, ed.x, j);
            float vj = __int_as_float(__shfl_sync(0xffffffffu, ed.y, j));
            __half2 hv = *reinterpret_cast<const __half2*>(
                &xin[(size_t)cj * DIM + lane * 2]);
            float2 xv = __half22float2(hv);
            acc.x = fmaf(vj, xv.x, acc.x);
            acc.y = fmaf(vj, xv.y, acc.y);
        }
    }
    if (base < e) {
        int rem = e - base;
        int2 ed = (base + lane < e) ? g_edge[base + lane] : make_int2(0, 0);
        for (int j = 0; j < rem; j++) {
            int   cj = __shfl_sync(0xffffffffu, ed.x, j);
            float vj = __int_as_float(__shfl_sync(0xffffffffu, ed.y, j));
            __half2 hv = *reinterpret_cast<const __half2*>(
                &xin[(size_t)cj * DIM + lane * 2]);
            float2 xv = __half22float2(hv);
            acc.x = fmaf(vj, xv.x, acc.x);
            acc.y = fmaf(vj, xv.y, acc.y);
        }
    }

    size_t o = (size_t)gw * DIM + lane * 2;

    if (write_x) {
        *reinterpret_cast<__half2*>(&xout[o]) = __floats2half2_rn(acc.x, acc.y);
    }

    float2 basev;
    if (first) {
        basev = *reinterpret_cast<const float2*>(&emb[o]);
    } else {
        basev = *reinterpret_cast<const float2*>(&out[o]);
    }
    float2 ov;
    ov.x = fmaf(coeff, acc.x, basev.x);
    ov.y = fmaf(coeff, acc.y, basev.y);
    *reinterpret_cast<float2*>(&out[o]) = ov;
}

// ---------------- launch ------------------------------------------------------
extern "C" void kernel_launch(void* const* d_in, const int* in_sizes, int n_in,
                              void* d_out, int out_size) {
    const int*   rows = (const int*)d_in[0];
    const int*   cols = (const int*)d_in[1];
    const float* vals = (const float*)d_in[2];
    const float* emb  = (const float*)d_in[3];
    float*       out  = (float*)d_out;

    (void)in_sizes; (void)n_in; (void)out_size;

    static __half* h0 = nullptr;
    static __half* h1 = nullptr;
    if (!h0) {
        void* p;
        cudaGetSymbolAddress(&p, g_h0); h0 = (__half*)p;
        cudaGetSymbolAddress(&p, g_h1); h1 = (__half*)p;
    }

    // ---- CSR build + emb conversion (independent streams of work) ----
    k_zero_cnt<<<256, 256>>>();
    k_conv_emb<<<2048, 256>>>(emb);
    k_hist<<<2048, 256>>>(rows);
    k_chunksum<<<NB, 256>>>();
    k_scan_bsum<<<1, 256>>>();
    k_writeptr<<<NB, 1024>>>();
    k_scatter<<<2048, 256>>>(rows, cols, vals);

    // ---- 3 SpMM layers, fused output accumulation ----
    const int threads = 256;
    const int blocks  = (NN * 32 + threads - 1) / threads;  // warp per row

    // layer 1: y1 = A @ emb_h ; out = emb + y1/2 ; h1 = (half)y1
    k_spmm<<<blocks, threads>>>(h0, h1, out, emb, 1.0f / 2.0f, 1, 1);
    // layer 2: y2 = A @ y1 ; out += y2/3 ; h0 = (half)y2 (emb_h dead now)
    k_spmm<<<blocks, threads>>>(h1, h0, out, emb, 1.0f / 3.0f, 0, 1);
    // layer 3: y3 = A @ y2 ; out += y3/4 ; no x write
    k_spmm<<<blocks, threads>>>(h0, (__half*)nullptr, out, emb, 1.0f / 4.0f, 0, 0);
}